// round 4
// baseline (speedup 1.0000x reference)
#include <cuda_runtime.h>
#include <math.h>

#define S 4096
#define E 768
#define Hh 12
#define D 64
#define Wb 256
#define TT 513          // band width 2W+1
#define TQ 32           // qk: query rows per CTA
#define TQP 64          // pv: query rows per CTA
#define NKB 9           // 64-wide key blocks
#define NEGV -1000000000.0f
#define SCALE 0.125f    // 1/sqrt(64)

// ---------------- scratch (static __device__, no allocations) ----------------
__device__ float g_q [S*E];
__device__ float g_k [S*E];
__device__ float g_v [S*E];
__device__ float g_cq[S*E];
__device__ float g_ck[S*E];
__device__ float g_lam[S*Hh];

// ---------------- projection GEMM: C = (A @ W + b) * scale ----------------
#define BM 128
#define BN 128
#define BK 16

__global__ __launch_bounds__(256, 2) void gemm5_kernel(
    const float* __restrict__ hs, const float* __restrict__ ce,
    const float* __restrict__ Wq,  const float* __restrict__ bq,
    const float* __restrict__ Wk,  const float* __restrict__ bk,
    const float* __restrict__ Wv,  const float* __restrict__ bv,
    const float* __restrict__ Wcq, const float* __restrict__ bcq,
    const float* __restrict__ Wck, const float* __restrict__ bck)
{
    const int which = blockIdx.z;
    const float* A;
    const float* Wt;
    const float* bias;
    float scale = 1.0f;
    float* C;
    switch (which) {
        case 0: A = hs; Wt = Wq;  bias = bq;  C = g_q;  break;
        case 1: A = hs; Wt = Wk;  bias = bk;  C = g_k;  break;
        case 2: A = hs; Wt = Wv;  bias = bv;  C = g_v;  break;
        case 3: A = ce; Wt = Wcq; bias = bcq; C = g_cq; scale = SCALE; break;
        default:A = ce; Wt = Wck; bias = bck; C = g_ck; break;
    }

    __shared__ float sA[2][BK][BM + 4];   // double-buffered A^T tile
    __shared__ float sB[2][BK][BN];

    const int tid = threadIdx.x;
    const int m0 = blockIdx.y * BM;
    const int n0 = blockIdx.x * BN;
    const int rg = tid >> 4;            // rows rg*8..rg*8+7
    const int cg = tid & 15;            // cols cg*8..cg*8+7
    const int la_m = tid >> 1;          // 0..127
    const int la_k = (tid & 1) << 3;    // 0 or 8
    const int lb_k = tid >> 4;          // 0..15
    const int lb_n = (tid & 15) << 3;   // 0..120

    const float* Arow = A  + (size_t)(m0 + la_m) * E + la_k;
    const float* Brow = Wt + (size_t)lb_k * E + n0 + lb_n;

    float acc[8][8];
    #pragma unroll
    for (int i = 0; i < 8; i++)
        #pragma unroll
        for (int j = 0; j < 8; j++) acc[i][j] = 0.f;

    // preload tile 0 into buffer 0
    {
        float4 a0 = *(const float4*)(Arow);
        float4 a1 = *(const float4*)(Arow + 4);
        float4 b0 = *(const float4*)(Brow);
        float4 b1 = *(const float4*)(Brow + 4);
        sA[0][la_k + 0][la_m] = a0.x; sA[0][la_k + 1][la_m] = a0.y;
        sA[0][la_k + 2][la_m] = a0.z; sA[0][la_k + 3][la_m] = a0.w;
        sA[0][la_k + 4][la_m] = a1.x; sA[0][la_k + 5][la_m] = a1.y;
        sA[0][la_k + 6][la_m] = a1.z; sA[0][la_k + 7][la_m] = a1.w;
        *(float4*)&sB[0][lb_k][lb_n]     = b0;
        *(float4*)&sB[0][lb_k][lb_n + 4] = b1;
    }
    __syncthreads();

    int cur = 0;
    for (int k0 = 0; k0 < E; k0 += BK) {
        const bool more = (k0 + BK < E);
        float4 a0, a1, b0, b1;
        if (more) {
            a0 = *(const float4*)(Arow + k0 + BK);
            a1 = *(const float4*)(Arow + k0 + BK + 4);
            b0 = *(const float4*)(Brow + (size_t)(k0 + BK) * E);
            b1 = *(const float4*)(Brow + (size_t)(k0 + BK) * E + 4);
        }

        #pragma unroll
        for (int kk = 0; kk < BK; kk++) {
            float4 af0 = *(const float4*)&sA[cur][kk][rg * 8];
            float4 af1 = *(const float4*)&sA[cur][kk][rg * 8 + 4];
            float4 bf0 = *(const float4*)&sB[cur][kk][cg * 8];
            float4 bf1 = *(const float4*)&sB[cur][kk][cg * 8 + 4];
            float a_[8] = {af0.x, af0.y, af0.z, af0.w, af1.x, af1.y, af1.z, af1.w};
            float b_[8] = {bf0.x, bf0.y, bf0.z, bf0.w, bf1.x, bf1.y, bf1.z, bf1.w};
            #pragma unroll
            for (int i = 0; i < 8; i++)
                #pragma unroll
                for (int j = 0; j < 8; j++)
                    acc[i][j] += a_[i] * b_[j];
        }

        if (more) {
            int nxt = cur ^ 1;
            sA[nxt][la_k + 0][la_m] = a0.x; sA[nxt][la_k + 1][la_m] = a0.y;
            sA[nxt][la_k + 2][la_m] = a0.z; sA[nxt][la_k + 3][la_m] = a0.w;
            sA[nxt][la_k + 4][la_m] = a1.x; sA[nxt][la_k + 5][la_m] = a1.y;
            sA[nxt][la_k + 6][la_m] = a1.z; sA[nxt][la_k + 7][la_m] = a1.w;
            *(float4*)&sB[nxt][lb_k][lb_n]     = b0;
            *(float4*)&sB[nxt][lb_k][lb_n + 4] = b1;
            __syncthreads();
            cur = nxt;
        }
    }

    float4 bv0 = *(const float4*)&bias[n0 + cg * 8];
    float4 bv1 = *(const float4*)&bias[n0 + cg * 8 + 4];
    float bb[8] = {bv0.x, bv0.y, bv0.z, bv0.w, bv1.x, bv1.y, bv1.z, bv1.w};
    #pragma unroll
    for (int i = 0; i < 8; i++) {
        int m = m0 + rg * 8 + i;
        float4 o0, o1;
        o0.x = (acc[i][0] + bb[0]) * scale;
        o0.y = (acc[i][1] + bb[1]) * scale;
        o0.z = (acc[i][2] + bb[2]) * scale;
        o0.w = (acc[i][3] + bb[3]) * scale;
        o1.x = (acc[i][4] + bb[4]) * scale;
        o1.y = (acc[i][5] + bb[5]) * scale;
        o1.z = (acc[i][6] + bb[6]) * scale;
        o1.w = (acc[i][7] + bb[7]) * scale;
        *(float4*)&C[(size_t)m * E + n0 + cg * 8]     = o0;
        *(float4*)&C[(size_t)m * E + n0 + cg * 8 + 4] = o1;
    }
}

// ---------------- lam ----------------
__global__ __launch_bounds__(256) void lam_kernel(
    const float* __restrict__ Wlqc, const float* __restrict__ blqc,
    const float* __restrict__ Wlqq, const float* __restrict__ blqq,
    const float* __restrict__ Wlkc, const float* __restrict__ blkc,
    const float* __restrict__ Wlkk, const float* __restrict__ blkk)
{
    int gw   = (blockIdx.x * blockDim.x + threadIdx.x) >> 5;
    int lane = threadIdx.x & 31;
    if (gw >= S * Hh) return;
    int s = gw / Hh, h = gw % Hh;
    size_t base = (size_t)s * E + h * D;

    float a = g_cq[base + lane] * Wlqc[lane] + g_cq[base + lane + 32] * Wlqc[lane + 32]
            + g_q [base + lane] * Wlqq[lane] + g_q [base + lane + 32] * Wlqq[lane + 32];
    float b = g_ck[base + lane] * Wlkc[lane] + g_ck[base + lane + 32] * Wlkc[lane + 32]
            + g_k [base + lane] * Wlkk[lane] + g_k [base + lane + 32] * Wlkk[lane + 32];
    #pragma unroll
    for (int o = 16; o; o >>= 1) {
        a += __shfl_xor_sync(0xffffffffu, a, o);
        b += __shfl_xor_sync(0xffffffffu, b, o);
    }
    if (lane == 0) {
        float lq = 1.f / (1.f + __expf(-(a + blqc[0] + blqq[0])));
        float lk = 1.f / (1.f + __expf(-(b + blkc[0] + blkk[0])));
        g_lam[gw] = 1.f - lq - lk;
    }
}

// ---------------- QK + softmax + combine, band in registers ----------------
// 512 threads: thread = (row r = tid>>4 in 0..31, colgroup cg = tid&15 -> cols 4cg..4cg+3)
// Band per thread: 1 row x 4 cols x 9 blocks = 36 attn + 36 quasi floats.
#define KSTR 64
#define QK_SMEM_FLOATS (2048 + 2048 + 64*KSTR + 64*KSTR + 64)

__global__ __launch_bounds__(512, 1) void qk_kernel(
    const int* __restrict__ amask, float* __restrict__ npout)
{
    extern __shared__ float sm[];
    float* sQT  = sm;                  // [64][32]  q^T (pre-scaled)
    float* sCQT = sm + 2048;           // [64][32]  cq^T
    float* sKT  = sm + 4096;           // [64][64]  k^T  ([d][c])
    float* sCKT = sm + 4096 + 4096;    // [64][64]  cq key^T
    float* sFm  = sm + 4096 + 8192;    // [64]

    const int h   = blockIdx.y;
    const int q0  = blockIdx.x * TQ;
    const int tid = threadIdx.x;
    const int r   = tid >> 4;          // 0..31 (this thread's row)
    const int cg  = tid & 15;
    const int c0  = cg << 2;           // cols c0..c0+3 of each 64-block

    // load q/cq transposed (q scaled here; cq pre-scaled by projection)
    {
        int lr = tid >> 4;             // 0..31
        int d0 = (tid & 15) << 2;      // 0..60
        const float4* qp  = (const float4*)(g_q  + (size_t)(q0 + lr) * E + h * D + d0);
        const float4* cqp = (const float4*)(g_cq + (size_t)(q0 + lr) * E + h * D + d0);
        float4 q1 = qp[0], c1 = cqp[0];
        sQT[(d0+0)*TQ + lr] = q1.x * SCALE; sQT[(d0+1)*TQ + lr] = q1.y * SCALE;
        sQT[(d0+2)*TQ + lr] = q1.z * SCALE; sQT[(d0+3)*TQ + lr] = q1.w * SCALE;
        sCQT[(d0+0)*TQ + lr] = c1.x; sCQT[(d0+1)*TQ + lr] = c1.y;
        sCQT[(d0+2)*TQ + lr] = c1.z; sCQT[(d0+3)*TQ + lr] = c1.w;
    }

    float aA[NKB*4];   // attn band (then exp values)
    float aQ[NKB*4];   // sigmoid(quasi) band

    const int lc  = tid >> 3;          // 0..63 tile-load column (key index)
    const int ld0 = (tid & 7) << 3;    // 0,8,...,56

    #pragma unroll
    for (int b = 0; b < NKB; b++) {
        const int kb0 = q0 - Wb + b * 64;
        __syncthreads();   // protect previous block's smem reads
        {
            int j = kb0 + lc;
            bool ok = (j >= 0) && (j < S);
            const float4* kp = (const float4*)(g_k  + (size_t)(ok ? j : 0) * E + h * D + ld0);
            const float4* cp = (const float4*)(g_cq + (size_t)(ok ? j : 0) * E + h * D + ld0);
            #pragma unroll
            for (int u4 = 0; u4 < 2; u4++) {
                float4 kv = ok ? kp[u4] : make_float4(0.f,0.f,0.f,0.f);
                float4 cv = ok ? cp[u4] : make_float4(0.f,0.f,0.f,0.f);
                int dd = ld0 + u4 * 4;
                sKT [(dd+0)*KSTR + lc] = kv.x; sKT [(dd+1)*KSTR + lc] = kv.y;
                sKT [(dd+2)*KSTR + lc] = kv.z; sKT [(dd+3)*KSTR + lc] = kv.w;
                sCKT[(dd+0)*KSTR + lc] = cv.x; sCKT[(dd+1)*KSTR + lc] = cv.y;
                sCKT[(dd+2)*KSTR + lc] = cv.z; sCKT[(dd+3)*KSTR + lc] = cv.w;
            }
            if (tid < 64) {
                int jj = kb0 + tid;
                sFm[tid] = (jj >= 0 && jj < S && amask[jj] != 0) ? -10000.f : 0.f;
            }
        }
        __syncthreads();

        float acc[4] = {0.f,0.f,0.f,0.f};
        float acq[4] = {0.f,0.f,0.f,0.f};
        #pragma unroll 8
        for (int kk = 0; kk < 64; kk++) {
            float qv  = sQT [kk*TQ + r];
            float cqv = sCQT[kk*TQ + r];
            float4 kv  = *(const float4*)&sKT [kk*KSTR + c0];
            float4 ckv = *(const float4*)&sCKT[kk*KSTR + c0];
            acc[0] += qv*kv.x;  acc[1] += qv*kv.y;
            acc[2] += qv*kv.z;  acc[3] += qv*kv.w;
            acq[0] += cqv*ckv.x; acq[1] += cqv*ckv.y;
            acq[2] += cqv*ckv.z; acq[3] += cqv*ckv.w;
        }

        // epilogue into register band
        #pragma unroll
        for (int jx = 0; jx < 4; jx++) {
            int c = c0 + jx;
            int t = b * 64 + c - r;
            int j = kb0 + c;
            bool valid = (t >= 0) && (t <= 512) && (j >= 0) && (j < S);
            float fm = sFm[c];
            aA[b*4+jx] = valid ? (acc[jx] + fm) : NEGV;
            float sg = 1.f / (1.f + __expf(-(acq[jx] + fm)));
            aQ[b*4+jx] = valid ? sg : 0.f;
        }
    }

    // softmax + combine + write new_probs (16 col-threads per row; half-warp shuffles)
    {
        int ig = q0 + r;
        float m = NEGV;
        #pragma unroll
        for (int x = 0; x < NKB*4; x++) m = fmaxf(m, aA[x]);
        #pragma unroll
        for (int o = 8; o; o >>= 1) m = fmaxf(m, __shfl_xor_sync(0xffffffffu, m, o));
        float ssum = 0.f;
        #pragma unroll
        for (int x = 0; x < NKB*4; x++) {
            float e = __expf(aA[x] - m);
            aA[x] = e;
            ssum += e;
        }
        #pragma unroll
        for (int o = 8; o; o >>= 1) ssum += __shfl_xor_sync(0xffffffffu, ssum, o);
        float inv  = 1.f / ssum;
        float lamv = g_lam[ig * Hh + h];
        bool  qm   = (amask[ig] != 0);
        float* nprow = npout + ((size_t)ig * Hh + h) * TT;
        #pragma unroll
        for (int b = 0; b < NKB; b++) {
            #pragma unroll
            for (int jx = 0; jx < 4; jx++) {
                int t = b * 64 + c0 + jx - r;
                float np = aA[b*4+jx] * inv + lamv * aQ[b*4+jx];
                if (qm) np = 0.f;
                if (t >= 0 && t <= 512) nprow[t] = np;
            }
        }
    }
}

// ---------------- PV: out = band_pv(new_probs, v) ----------------
// TQP=64 rows per CTA: band exactly 9 x 64 blocks, no padding waste.
// 256 threads: rg = tid>>4 -> rows 4rg..4rg+3, dg = tid&15 -> d 4dg..4dg+3
#define PSTR 68
#define VSTR 68

__global__ __launch_bounds__(256) void pv_kernel(
    float* __restrict__ outp, const float* __restrict__ npout)
{
    __shared__ float sP[TQP * PSTR];   // [64][68]
    __shared__ float sV[64 * VSTR];    // [64][68]

    const int h   = blockIdx.y;
    const int q0  = blockIdx.x * TQP;
    const int tid = threadIdx.x;
    const int rg  = tid >> 4;          // 0..15 -> rows 4rg..4rg+3
    const int dg  = tid & 15;          // d = 4dg..4dg+3

    float acc[4][4];
    #pragma unroll
    for (int i = 0; i < 4; i++)
        #pragma unroll
        for (int j = 0; j < 4; j++) acc[i][j] = 0.f;

    for (int b = 0; b < NKB; b++) {
        int kb0 = q0 - Wb + b * 64;
        __syncthreads();
        // load p tile: row lr, cols c0l..c0l+15
        {
            int lr  = tid >> 2;            // 0..63
            int c0l = (tid & 3) << 4;      // 0,16,32,48
            const float* nprow = npout + ((size_t)(q0 + lr) * Hh + h) * TT;
            #pragma unroll
            for (int x4 = 0; x4 < 4; x4++) {
                int t0 = b * 64 + c0l + x4 * 4 - lr;
                float4 pv4;
                pv4.x = (t0+0 >= 0 && t0+0 <= 512) ? nprow[t0+0] : 0.f;
                pv4.y = (t0+1 >= 0 && t0+1 <= 512) ? nprow[t0+1] : 0.f;
                pv4.z = (t0+2 >= 0 && t0+2 <= 512) ? nprow[t0+2] : 0.f;
                pv4.w = (t0+3 >= 0 && t0+3 <= 512) ? nprow[t0+3] : 0.f;
                *(float4*)&sP[lr * PSTR + c0l + x4 * 4] = pv4;
            }
        }
        // load v tile [c][d]
        {
            int c   = tid >> 2;            // 0..63
            int d0l = (tid & 3) << 4;      // 0,16,32,48
            int j = kb0 + c;
            bool ok = (j >= 0) && (j < S);
            const float4* vp = (const float4*)(g_v + (size_t)(ok ? j : 0) * E + h * D + d0l);
            #pragma unroll
            for (int u4 = 0; u4 < 4; u4++) {
                float4 x = ok ? vp[u4] : make_float4(0.f,0.f,0.f,0.f);
                *(float4*)&sV[c * VSTR + d0l + u4 * 4] = x;
            }
        }
        __syncthreads();

        #pragma unroll 4
        for (int c = 0; c < 64; c++) {
            float4 vv = *(const float4*)&sV[c * VSTR + 4 * dg];
            float p0 = sP[(4*rg+0) * PSTR + c];
            float p1 = sP[(4*rg+1) * PSTR + c];
            float p2 = sP[(4*rg+2) * PSTR + c];
            float p3 = sP[(4*rg+3) * PSTR + c];
            acc[0][0] += p0*vv.x; acc[0][1] += p0*vv.y; acc[0][2] += p0*vv.z; acc[0][3] += p0*vv.w;
            acc[1][0] += p1*vv.x; acc[1][1] += p1*vv.y; acc[1][2] += p1*vv.z; acc[1][3] += p1*vv.w;
            acc[2][0] += p2*vv.x; acc[2][1] += p2*vv.y; acc[2][2] += p2*vv.z; acc[2][3] += p2*vv.w;
            acc[3][0] += p3*vv.x; acc[3][1] += p3*vv.y; acc[3][2] += p3*vv.z; acc[3][3] += p3*vv.w;
        }
    }

    #pragma unroll
    for (int i = 0; i < 4; i++) {
        float4 o;
        o.x = acc[i][0]; o.y = acc[i][1]; o.z = acc[i][2]; o.w = acc[i][3];
        *(float4*)(outp + (size_t)(q0 + 4*rg + i) * E + h * D + 4 * dg) = o;
    }
}

// ---------------- launch ----------------
extern "C" void kernel_launch(void* const* d_in, const int* in_sizes, int n_in,
                              void* d_out, int out_size)
{
    (void)in_sizes; (void)n_in; (void)out_size;

    const float* hs    = (const float*)d_in[0];
    const float* ce    = (const float*)d_in[1];
    const int*   amask = (const int*)  d_in[2];
    // d_in[3] is is_index_masked == (attention_mask != 0); derived from amask.
    const float* Wq   = (const float*)d_in[4];
    const float* bq   = (const float*)d_in[5];
    const float* Wk   = (const float*)d_in[6];
    const float* bk   = (const float*)d_in[7];
    const float* Wv   = (const float*)d_in[8];
    const float* bv   = (const float*)d_in[9];
    const float* Wcq  = (const float*)d_in[10];
    const float* bcq  = (const float*)d_in[11];
    const float* Wck  = (const float*)d_in[12];
    const float* bck  = (const float*)d_in[13];
    const float* Wlqc = (const float*)d_in[14];
    const float* blqc = (const float*)d_in[15];
    const float* Wlqq = (const float*)d_in[16];
    const float* blqq = (const float*)d_in[17];
    const float* Wlkc = (const float*)d_in[18];
    const float* blkc = (const float*)d_in[19];
    const float* Wlkk = (const float*)d_in[20];
    const float* blkk = (const float*)d_in[21];

    float* outp  = (float*)d_out;
    float* npout = outp + (size_t)S * E;   // tuple output: [out | new_probs]

    cudaFuncSetAttribute(qk_kernel, cudaFuncAttributeMaxDynamicSharedMemorySize,
                         QK_SMEM_FLOATS * 4);

    dim3 gg(E / BN, S / BM, 5);
    gemm5_kernel<<<gg, 256>>>(hs, ce, Wq, bq, Wk, bk, Wv, bv, Wcq, bcq, Wck, bck);

    lam_kernel<<<(S * Hh) / 8, 256>>>(Wlqc, blqc, Wlqq, blqq, Wlkc, blkc, Wlkk, blkk);

    qk_kernel<<<dim3(S / TQ, Hh), 512, QK_SMEM_FLOATS * 4>>>(amask, npout);

    pv_kernel<<<dim3(S / TQP, Hh), 256>>>(outp, npout);
}

// round 5
// speedup vs baseline: 1.2395x; 1.2395x over previous
#include <cuda_runtime.h>
#include <math.h>

#define S 4096
#define E 768
#define Hh 12
#define D 64
#define Wb 256
#define TT 513          // band width 2W+1
#define TQ 32           // qk: query rows per CTA
#define TQP 64          // pv: query rows per CTA
#define NKB 9           // 64-wide key blocks
#define NEGV -1000000000.0f
#define SCALE 0.125f    // 1/sqrt(64)

// ---------------- scratch (static __device__, no allocations) ----------------
__device__ float g_q [S*E];
__device__ float g_k [S*E];
__device__ float g_v [S*E];
__device__ float g_cq[S*E];
__device__ float g_ck[S*E];
__device__ float g_lam[S*Hh];

// ---------------- projection GEMM: C = (A @ W + b) * scale (R3 version) ----------------
#define BM 128
#define BN 128
#define BK 16

__global__ __launch_bounds__(256, 2) void gemm5_kernel(
    const float* __restrict__ hs, const float* __restrict__ ce,
    const float* __restrict__ Wq,  const float* __restrict__ bq,
    const float* __restrict__ Wk,  const float* __restrict__ bk,
    const float* __restrict__ Wv,  const float* __restrict__ bv,
    const float* __restrict__ Wcq, const float* __restrict__ bcq,
    const float* __restrict__ Wck, const float* __restrict__ bck)
{
    const int which = blockIdx.z;
    const float* A;
    const float* Wt;
    const float* bias;
    float scale = 1.0f;
    float* C;
    switch (which) {
        case 0: A = hs; Wt = Wq;  bias = bq;  C = g_q;  break;
        case 1: A = hs; Wt = Wk;  bias = bk;  C = g_k;  break;
        case 2: A = hs; Wt = Wv;  bias = bv;  C = g_v;  break;
        case 3: A = ce; Wt = Wcq; bias = bcq; C = g_cq; scale = SCALE; break;
        default:A = ce; Wt = Wck; bias = bck; C = g_ck; break;
    }

    __shared__ float sA[BK][BM + 4];   // A^T tile
    __shared__ float sB[BK][BN];

    const int tid = threadIdx.x;
    const int m0 = blockIdx.y * BM;
    const int n0 = blockIdx.x * BN;
    const int rg = tid >> 4;            // rows rg*8..rg*8+7
    const int cg = tid & 15;            // cols cg*8..cg*8+7
    const int la_m = tid >> 1;          // 0..127
    const int la_k = (tid & 1) << 3;    // 0 or 8
    const int lb_k = tid >> 4;          // 0..15
    const int lb_n = (tid & 15) << 3;   // 0..120

    const float* Arow = A  + (size_t)(m0 + la_m) * E + la_k;
    const float* Brow = Wt + (size_t)lb_k * E + n0 + lb_n;

    float acc[8][8];
    #pragma unroll
    for (int i = 0; i < 8; i++)
        #pragma unroll
        for (int j = 0; j < 8; j++) acc[i][j] = 0.f;

    float4 a0 = *(const float4*)(Arow);
    float4 a1 = *(const float4*)(Arow + 4);
    float4 b0 = *(const float4*)(Brow);
    float4 b1 = *(const float4*)(Brow + 4);

    for (int k0 = 0; k0 < E; k0 += BK) {
        sA[la_k + 0][la_m] = a0.x; sA[la_k + 1][la_m] = a0.y;
        sA[la_k + 2][la_m] = a0.z; sA[la_k + 3][la_m] = a0.w;
        sA[la_k + 4][la_m] = a1.x; sA[la_k + 5][la_m] = a1.y;
        sA[la_k + 6][la_m] = a1.z; sA[la_k + 7][la_m] = a1.w;
        *(float4*)&sB[lb_k][lb_n]     = b0;
        *(float4*)&sB[lb_k][lb_n + 4] = b1;
        __syncthreads();

        float4 na0 = a0, na1 = a1, nb0 = b0, nb1 = b1;
        if (k0 + BK < E) {
            na0 = *(const float4*)(Arow + k0 + BK);
            na1 = *(const float4*)(Arow + k0 + BK + 4);
            nb0 = *(const float4*)(Brow + (size_t)(k0 + BK) * E);
            nb1 = *(const float4*)(Brow + (size_t)(k0 + BK) * E + 4);
        }

        #pragma unroll
        for (int kk = 0; kk < BK; kk++) {
            float4 af0 = *(const float4*)&sA[kk][rg * 8];
            float4 af1 = *(const float4*)&sA[kk][rg * 8 + 4];
            float4 bf0 = *(const float4*)&sB[kk][cg * 8];
            float4 bf1 = *(const float4*)&sB[kk][cg * 8 + 4];
            float a_[8] = {af0.x, af0.y, af0.z, af0.w, af1.x, af1.y, af1.z, af1.w};
            float b_[8] = {bf0.x, bf0.y, bf0.z, bf0.w, bf1.x, bf1.y, bf1.z, bf1.w};
            #pragma unroll
            for (int i = 0; i < 8; i++)
                #pragma unroll
                for (int j = 0; j < 8; j++)
                    acc[i][j] += a_[i] * b_[j];
        }
        __syncthreads();
        a0 = na0; a1 = na1; b0 = nb0; b1 = nb1;
    }

    float4 bv0 = *(const float4*)&bias[n0 + cg * 8];
    float4 bv1 = *(const float4*)&bias[n0 + cg * 8 + 4];
    float bb[8] = {bv0.x, bv0.y, bv0.z, bv0.w, bv1.x, bv1.y, bv1.z, bv1.w};
    #pragma unroll
    for (int i = 0; i < 8; i++) {
        int m = m0 + rg * 8 + i;
        float4 o0, o1;
        o0.x = (acc[i][0] + bb[0]) * scale;
        o0.y = (acc[i][1] + bb[1]) * scale;
        o0.z = (acc[i][2] + bb[2]) * scale;
        o0.w = (acc[i][3] + bb[3]) * scale;
        o1.x = (acc[i][4] + bb[4]) * scale;
        o1.y = (acc[i][5] + bb[5]) * scale;
        o1.z = (acc[i][6] + bb[6]) * scale;
        o1.w = (acc[i][7] + bb[7]) * scale;
        *(float4*)&C[(size_t)m * E + n0 + cg * 8]     = o0;
        *(float4*)&C[(size_t)m * E + n0 + cg * 8 + 4] = o1;
    }
}

// ---------------- lam ----------------
__global__ __launch_bounds__(256) void lam_kernel(
    const float* __restrict__ Wlqc, const float* __restrict__ blqc,
    const float* __restrict__ Wlqq, const float* __restrict__ blqq,
    const float* __restrict__ Wlkc, const float* __restrict__ blkc,
    const float* __restrict__ Wlkk, const float* __restrict__ blkk)
{
    int gw   = (blockIdx.x * blockDim.x + threadIdx.x) >> 5;
    int lane = threadIdx.x & 31;
    if (gw >= S * Hh) return;
    int s = gw / Hh, h = gw % Hh;
    size_t base = (size_t)s * E + h * D;

    float a = g_cq[base + lane] * Wlqc[lane] + g_cq[base + lane + 32] * Wlqc[lane + 32]
            + g_q [base + lane] * Wlqq[lane] + g_q [base + lane + 32] * Wlqq[lane + 32];
    float b = g_ck[base + lane] * Wlkc[lane] + g_ck[base + lane + 32] * Wlkc[lane + 32]
            + g_k [base + lane] * Wlkk[lane] + g_k [base + lane + 32] * Wlkk[lane + 32];
    #pragma unroll
    for (int o = 16; o; o >>= 1) {
        a += __shfl_xor_sync(0xffffffffu, a, o);
        b += __shfl_xor_sync(0xffffffffu, b, o);
    }
    if (lane == 0) {
        float lq = 1.f / (1.f + __expf(-(a + blqc[0] + blqq[0])));
        float lk = 1.f / (1.f + __expf(-(b + blkc[0] + blkk[0])));
        g_lam[gw] = 1.f - lq - lk;
    }
}

// ---------------- quasi kernel: npout[t] = lam * sigmoid(cq.cq + mask)  (stream-through) ----------------
#define KSTR 64

__global__ __launch_bounds__(256) void quasi_kernel(
    const int* __restrict__ amask, float* __restrict__ npout)
{
    __shared__ float sCQT[64 * TQ];    // cq^T for query rows
    __shared__ float sCKT[64 * KSTR];  // cq key-block^T
    __shared__ float sFm[64];

    const int h   = blockIdx.y;
    const int q0  = blockIdx.x * TQ;
    const int tid = threadIdx.x;
    const int rg  = tid >> 4;          // 0..15
    const int cg  = tid & 15;
    const int r0  = rg << 1;           // rows r0, r0+1
    const int c0  = cg << 2;           // cols c0..c0+3

    // load cq^T (already scaled by projection)
    {
        int lr = tid >> 3;             // 0..31
        int d0 = (tid & 7) << 3;       // 8 floats each
        const float4* cqp = (const float4*)(g_cq + (size_t)(q0 + lr) * E + h * D + d0);
        float4 c1 = cqp[0], c2 = cqp[1];
        sCQT[(d0+0)*TQ + lr] = c1.x; sCQT[(d0+1)*TQ + lr] = c1.y;
        sCQT[(d0+2)*TQ + lr] = c1.z; sCQT[(d0+3)*TQ + lr] = c1.w;
        sCQT[(d0+4)*TQ + lr] = c2.x; sCQT[(d0+5)*TQ + lr] = c2.y;
        sCQT[(d0+6)*TQ + lr] = c2.z; sCQT[(d0+7)*TQ + lr] = c2.w;
    }

    const float lam0 = g_lam[(q0 + r0 + 0) * Hh + h];
    const float lam1 = g_lam[(q0 + r0 + 1) * Hh + h];
    float* nprow0 = npout + ((size_t)(q0 + r0 + 0) * Hh + h) * TT;
    float* nprow1 = npout + ((size_t)(q0 + r0 + 1) * Hh + h) * TT;

    const int lc  = tid >> 2;          // 0..63
    const int ld0 = (tid & 3) << 4;    // 0,16,32,48

    for (int b = 0; b < NKB; b++) {
        const int kb0 = q0 - Wb + b * 64;
        __syncthreads();
        {
            int j = kb0 + lc;
            bool ok = (j >= 0) && (j < S);
            const float4* cp = (const float4*)(g_cq + (size_t)(ok ? j : 0) * E + h * D + ld0);
            #pragma unroll
            for (int u4 = 0; u4 < 4; u4++) {
                float4 cv = ok ? cp[u4] : make_float4(0.f,0.f,0.f,0.f);
                int dd = ld0 + u4 * 4;
                sCKT[(dd+0)*KSTR + lc] = cv.x; sCKT[(dd+1)*KSTR + lc] = cv.y;
                sCKT[(dd+2)*KSTR + lc] = cv.z; sCKT[(dd+3)*KSTR + lc] = cv.w;
            }
            if (tid < 64) {
                int jj = kb0 + tid;
                sFm[tid] = (jj >= 0 && jj < S && amask[jj] != 0) ? -10000.f : 0.f;
            }
        }
        __syncthreads();

        float acq[2][4] = {{0.f,0.f,0.f,0.f},{0.f,0.f,0.f,0.f}};
        #pragma unroll 8
        for (int kk = 0; kk < 64; kk++) {
            float2 cqv = *(const float2*)&sCQT[kk*TQ  + r0];
            float4 ckv = *(const float4*)&sCKT[kk*KSTR + c0];
            acq[0][0] += cqv.x*ckv.x; acq[0][1] += cqv.x*ckv.y;
            acq[0][2] += cqv.x*ckv.z; acq[0][3] += cqv.x*ckv.w;
            acq[1][0] += cqv.y*ckv.x; acq[1][1] += cqv.y*ckv.y;
            acq[1][2] += cqv.y*ckv.z; acq[1][3] += cqv.y*ckv.w;
        }

        #pragma unroll
        for (int jx = 0; jx < 4; jx++) {
            int c = c0 + jx;
            int j = kb0 + c;
            bool okj = (j >= 0) && (j < S);
            float fm = sFm[c];
            // row 0
            {
                int t = b * 64 + c - (r0 + 0);
                if (t >= 0 && t <= 512) {
                    float v = okj ? lam0 / (1.f + __expf(-(acq[0][jx] + fm))) : 0.f;
                    nprow0[t] = v;
                }
            }
            // row 1
            {
                int t = b * 64 + c - (r0 + 1);
                if (t >= 0 && t <= 512) {
                    float v = okj ? lam1 / (1.f + __expf(-(acq[1][jx] + fm))) : 0.f;
                    nprow1[t] = v;
                }
            }
        }
    }
}

// ---------------- attn kernel: softmax band + combine with staged quasi ----------------
__global__ __launch_bounds__(256, 2) void attn_kernel(
    const int* __restrict__ amask, float* __restrict__ npout)
{
    __shared__ float sQT[64 * TQ];     // q^T (pre-scaled)
    __shared__ float sKT[64 * KSTR];   // k^T
    __shared__ float sFm[64];

    const int h   = blockIdx.y;
    const int q0  = blockIdx.x * TQ;
    const int tid = threadIdx.x;
    const int rg  = tid >> 4;
    const int cg  = tid & 15;
    const int r0  = rg << 1;
    const int c0  = cg << 2;

    {
        int lr = tid >> 3;
        int d0 = (tid & 7) << 3;
        const float4* qp = (const float4*)(g_q + (size_t)(q0 + lr) * E + h * D + d0);
        float4 q1 = qp[0], q2 = qp[1];
        sQT[(d0+0)*TQ + lr] = q1.x * SCALE; sQT[(d0+1)*TQ + lr] = q1.y * SCALE;
        sQT[(d0+2)*TQ + lr] = q1.z * SCALE; sQT[(d0+3)*TQ + lr] = q1.w * SCALE;
        sQT[(d0+4)*TQ + lr] = q2.x * SCALE; sQT[(d0+5)*TQ + lr] = q2.y * SCALE;
        sQT[(d0+6)*TQ + lr] = q2.z * SCALE; sQT[(d0+7)*TQ + lr] = q2.w * SCALE;
    }

    float aA[2][NKB*4];   // attn band (scores, then exp)

    const int lc  = tid >> 2;
    const int ld0 = (tid & 3) << 4;

    #pragma unroll
    for (int b = 0; b < NKB; b++) {
        const int kb0 = q0 - Wb + b * 64;
        __syncthreads();
        {
            int j = kb0 + lc;
            bool ok = (j >= 0) && (j < S);
            const float4* kp = (const float4*)(g_k + (size_t)(ok ? j : 0) * E + h * D + ld0);
            #pragma unroll
            for (int u4 = 0; u4 < 4; u4++) {
                float4 kv = ok ? kp[u4] : make_float4(0.f,0.f,0.f,0.f);
                int dd = ld0 + u4 * 4;
                sKT[(dd+0)*KSTR + lc] = kv.x; sKT[(dd+1)*KSTR + lc] = kv.y;
                sKT[(dd+2)*KSTR + lc] = kv.z; sKT[(dd+3)*KSTR + lc] = kv.w;
            }
            if (tid < 64) {
                int jj = kb0 + tid;
                sFm[tid] = (jj >= 0 && jj < S && amask[jj] != 0) ? -10000.f : 0.f;
            }
        }
        __syncthreads();

        float acc[2][4] = {{0.f,0.f,0.f,0.f},{0.f,0.f,0.f,0.f}};
        #pragma unroll 8
        for (int kk = 0; kk < 64; kk++) {
            float2 qv = *(const float2*)&sQT[kk*TQ  + r0];
            float4 kv = *(const float4*)&sKT[kk*KSTR + c0];
            acc[0][0] += qv.x*kv.x; acc[0][1] += qv.x*kv.y;
            acc[0][2] += qv.x*kv.z; acc[0][3] += qv.x*kv.w;
            acc[1][0] += qv.y*kv.x; acc[1][1] += qv.y*kv.y;
            acc[1][2] += qv.y*kv.z; acc[1][3] += qv.y*kv.w;
        }

        #pragma unroll
        for (int i = 0; i < 2; i++) {
            int r = r0 + i;
            #pragma unroll
            for (int jx = 0; jx < 4; jx++) {
                int c = c0 + jx;
                int t = b * 64 + c - r;
                int j = kb0 + c;
                bool valid = (t >= 0) && (t <= 512) && (j >= 0) && (j < S);
                aA[i][b*4+jx] = valid ? (acc[i][jx] + sFm[c]) : NEGV;
            }
        }
    }

    // softmax + combine with staged lam*sigmoid(quasi) + write
    #pragma unroll
    for (int i = 0; i < 2; i++) {
        int r  = r0 + i;
        int ig = q0 + r;
        float m = NEGV;
        #pragma unroll
        for (int x = 0; x < NKB*4; x++) m = fmaxf(m, aA[i][x]);
        #pragma unroll
        for (int o = 8; o; o >>= 1) m = fmaxf(m, __shfl_xor_sync(0xffffffffu, m, o));
        float ssum = 0.f;
        #pragma unroll
        for (int x = 0; x < NKB*4; x++) {
            float e = __expf(aA[i][x] - m);
            aA[i][x] = e;
            ssum += e;
        }
        #pragma unroll
        for (int o = 8; o; o >>= 1) ssum += __shfl_xor_sync(0xffffffffu, ssum, o);
        float inv = 1.f / ssum;
        bool  qm  = (amask[ig] != 0);
        float* nprow = npout + ((size_t)ig * Hh + h) * TT;
        #pragma unroll
        for (int b = 0; b < NKB; b++) {
            #pragma unroll
            for (int jx = 0; jx < 4; jx++) {
                int t = b * 64 + c0 + jx - r;
                if (t >= 0 && t <= 512) {
                    float np = aA[i][b*4+jx] * inv + nprow[t];
                    nprow[t] = qm ? 0.f : np;
                }
            }
        }
    }
}

// ---------------- PV: out = band_pv(new_probs, v) (R4 version) ----------------
#define PSTR 68
#define VSTR 68

__global__ __launch_bounds__(256) void pv_kernel(
    float* __restrict__ outp, const float* __restrict__ npout)
{
    __shared__ float sP[TQP * PSTR];   // [64][68]
    __shared__ float sV[64 * VSTR];    // [64][68]

    const int h   = blockIdx.y;
    const int q0  = blockIdx.x * TQP;
    const int tid = threadIdx.x;
    const int rg  = tid >> 4;          // rows 4rg..4rg+3
    const int dg  = tid & 15;          // d = 4dg..4dg+3

    float acc[4][4];
    #pragma unroll
    for (int i = 0; i < 4; i++)
        #pragma unroll
        for (int j = 0; j < 4; j++) acc[i][j] = 0.f;

    for (int b = 0; b < NKB; b++) {
        int kb0 = q0 - Wb + b * 64;
        __syncthreads();
        {
            int lr  = tid >> 2;
            int c0l = (tid & 3) << 4;
            const float* nprow = npout + ((size_t)(q0 + lr) * Hh + h) * TT;
            #pragma unroll
            for (int x4 = 0; x4 < 4; x4++) {
                int t0 = b * 64 + c0l + x4 * 4 - lr;
                float4 pv4;
                pv4.x = (t0+0 >= 0 && t0+0 <= 512) ? nprow[t0+0] : 0.f;
                pv4.y = (t0+1 >= 0 && t0+1 <= 512) ? nprow[t0+1] : 0.f;
                pv4.z = (t0+2 >= 0 && t0+2 <= 512) ? nprow[t0+2] : 0.f;
                pv4.w = (t0+3 >= 0 && t0+3 <= 512) ? nprow[t0+3] : 0.f;
                *(float4*)&sP[lr * PSTR + c0l + x4 * 4] = pv4;
            }
        }
        {
            int c   = tid >> 2;
            int d0l = (tid & 3) << 4;
            int j = kb0 + c;
            bool ok = (j >= 0) && (j < S);
            const float4* vp = (const float4*)(g_v + (size_t)(ok ? j : 0) * E + h * D + d0l);
            #pragma unroll
            for (int u4 = 0; u4 < 4; u4++) {
                float4 x = ok ? vp[u4] : make_float4(0.f,0.f,0.f,0.f);
                *(float4*)&sV[c * VSTR + d0l + u4 * 4] = x;
            }
        }
        __syncthreads();

        #pragma unroll 4
        for (int c = 0; c < 64; c++) {
            float4 vv = *(const float4*)&sV[c * VSTR + 4 * dg];
            float p0 = sP[(4*rg+0) * PSTR + c];
            float p1 = sP[(4*rg+1) * PSTR + c];
            float p2 = sP[(4*rg+2) * PSTR + c];
            float p3 = sP[(4*rg+3) * PSTR + c];
            acc[0][0] += p0*vv.x; acc[0][1] += p0*vv.y; acc[0][2] += p0*vv.z; acc[0][3] += p0*vv.w;
            acc[1][0] += p1*vv.x; acc[1][1] += p1*vv.y; acc[1][2] += p1*vv.z; acc[1][3] += p1*vv.w;
            acc[2][0] += p2*vv.x; acc[2][1] += p2*vv.y; acc[2][2] += p2*vv.z; acc[2][3] += p2*vv.w;
            acc[3][0] += p3*vv.x; acc[3][1] += p3*vv.y; acc[3][2] += p3*vv.z; acc[3][3] += p3*vv.w;
        }
    }

    #pragma unroll
    for (int i = 0; i < 4; i++) {
        float4 o;
        o.x = acc[i][0]; o.y = acc[i][1]; o.z = acc[i][2]; o.w = acc[i][3];
        *(float4*)(outp + (size_t)(q0 + 4*rg + i) * E + h * D + 4 * dg) = o;
    }
}

// ---------------- launch ----------------
extern "C" void kernel_launch(void* const* d_in, const int* in_sizes, int n_in,
                              void* d_out, int out_size)
{
    (void)in_sizes; (void)n_in; (void)out_size;

    const float* hs    = (const float*)d_in[0];
    const float* ce    = (const float*)d_in[1];
    const int*   amask = (const int*)  d_in[2];
    // d_in[3] is is_index_masked == (attention_mask != 0); derived from amask.
    const float* Wq   = (const float*)d_in[4];
    const float* bq   = (const float*)d_in[5];
    const float* Wk   = (const float*)d_in[6];
    const float* bk   = (const float*)d_in[7];
    const float* Wv   = (const float*)d_in[8];
    const float* bv   = (const float*)d_in[9];
    const float* Wcq  = (const float*)d_in[10];
    const float* bcq  = (const float*)d_in[11];
    const float* Wck  = (const float*)d_in[12];
    const float* bck  = (const float*)d_in[13];
    const float* Wlqc = (const float*)d_in[14];
    const float* blqc = (const float*)d_in[15];
    const float* Wlqq = (const float*)d_in[16];
    const float* blqq = (const float*)d_in[17];
    const float* Wlkc = (const float*)d_in[18];
    const float* blkc = (const float*)d_in[19];
    const float* Wlkk = (const float*)d_in[20];
    const float* blkk = (const float*)d_in[21];

    float* outp  = (float*)d_out;
    float* npout = outp + (size_t)S * E;   // tuple output: [out | new_probs]

    dim3 gg(E / BN, S / BM, 5);
    gemm5_kernel<<<gg, 256>>>(hs, ce, Wq, bq, Wk, bk, Wv, bv, Wcq, bcq, Wck, bck);

    lam_kernel<<<(S * Hh) / 8, 256>>>(Wlqc, blqc, Wlqq, blqq, Wlkc, blkc, Wlkk, blkk);

    quasi_kernel<<<dim3(S / TQ, Hh), 256>>>(amask, npout);

    attn_kernel<<<dim3(S / TQ, Hh), 256>>>(amask, npout);

    pv_kernel<<<dim3(S / TQP, Hh), 256>>>(outp, npout);
}

// round 7
// speedup vs baseline: 1.4861x; 1.1990x over previous
#include <cuda_runtime.h>
#include <math.h>
#include <stdint.h>

#define S 4096
#define E 768
#define Hh 12
#define D 64
#define Wb 256
#define TT 513          // band width 2W+1
#define TQ 32           // qk: query rows per CTA
#define TQP 64          // pv: query rows per CTA
#define NKB 9           // 64-wide key blocks
#define NEGV -1000000000.0f
#define SCALE 0.125f    // 1/sqrt(64)

// ---------------- scratch (static __device__, no allocations) ----------------
__device__ float g_q [S*E];
__device__ float g_k [S*E];
__device__ float g_v [S*E];
__device__ float g_cq[S*E];
__device__ float g_ck[S*E];
__device__ float g_lam[S*Hh];

// ---------------- projection GEMM (tf32 mma.sync): C = (A @ W + b) * scale ----------------
// CTA tile 128x64, k-slab 32. 256 threads = 8 warps (4 m x 2 n), warp tile 32x32.
#define GBM 128
#define GBN 64
#define GBK 32
#define ASTR 136   // sA[k][m] row stride (words): frag addr banks 8*(l&3)+(l>>2) -> conflict-free
#define BSTR 72    // sB[k][n] row stride (words): same property; 288B rows keep STS.128 aligned

__device__ __forceinline__ uint32_t f2tf32(float f) {
    uint32_t u;
    asm("cvt.rna.tf32.f32 %0, %1;" : "=r"(u) : "f"(f));
    return u;
}

__global__ __launch_bounds__(256) void gemm5_tc(
    const float* __restrict__ hs, const float* __restrict__ ce,
    const float* __restrict__ Wq,  const float* __restrict__ bq,
    const float* __restrict__ Wk,  const float* __restrict__ bk,
    const float* __restrict__ Wv,  const float* __restrict__ bv,
    const float* __restrict__ Wcq, const float* __restrict__ bcq,
    const float* __restrict__ Wck, const float* __restrict__ bck)
{
    const int which = blockIdx.z;
    const float* A;
    const float* Wt;
    const float* bias;
    float scale = 1.0f;
    float* C;
    switch (which) {
        case 0: A = hs; Wt = Wq;  bias = bq;  C = g_q;  break;
        case 1: A = hs; Wt = Wk;  bias = bk;  C = g_k;  break;
        case 2: A = hs; Wt = Wv;  bias = bv;  C = g_v;  break;
        case 3: A = ce; Wt = Wcq; bias = bcq; C = g_cq; scale = SCALE; break;
        default:A = ce; Wt = Wck; bias = bck; C = g_ck; break;
    }

    __shared__ uint32_t sA[GBK][ASTR];   // tf32 bits, [k][m]
    __shared__ uint32_t sB[GBK][BSTR];   // tf32 bits, [k][n]

    const int tid  = threadIdx.x;
    const int warp = tid >> 5;
    const int lane = tid & 31;
    const int wm   = warp & 3;           // 0..3 -> m offset wm*32
    const int wn   = warp >> 2;          // 0..1 -> n offset wn*32
    const int g    = lane >> 2;          // 0..7
    const int t4   = lane & 3;           // 0..3
    const int m0   = blockIdx.y * GBM;
    const int n0   = blockIdx.x * GBN;

    // A loader: thread -> row (tid&127), k base (tid>>7)*16, 16 floats along k
    const int am = tid & 127;
    const int ak = (tid >> 7) * 16;
    // B loader: thread -> k row (tid>>3), n base (tid&7)*8, 8 floats along n
    const int bk2 = tid >> 3;
    const int bn2 = (tid & 7) * 8;

    const float* Abase = A  + (size_t)(m0 + am) * E + ak;
    const float* Bbase = Wt + (size_t)bk2 * E + n0 + bn2;

    float acc[2][4][4];
    #pragma unroll
    for (int mt = 0; mt < 2; mt++)
        #pragma unroll
        for (int nt = 0; nt < 4; nt++)
            #pragma unroll
            for (int x = 0; x < 4; x++) acc[mt][nt][x] = 0.f;

    for (int k0 = 0; k0 < E; k0 += GBK) {
        // fill sA (scatter along k, conflict-free STS since m consecutive per warp)
        #pragma unroll
        for (int i = 0; i < 4; i++) {
            float4 v = *(const float4*)(Abase + k0 + i * 4);
            sA[ak + i*4 + 0][am] = f2tf32(v.x);
            sA[ak + i*4 + 1][am] = f2tf32(v.y);
            sA[ak + i*4 + 2][am] = f2tf32(v.z);
            sA[ak + i*4 + 3][am] = f2tf32(v.w);
        }
        // fill sB (vector STS.128 per 4 cols)
        #pragma unroll
        for (int i = 0; i < 2; i++) {
            float4 v = *(const float4*)(Bbase + (size_t)k0 * E + i * 4);
            uint4 u;
            u.x = f2tf32(v.x); u.y = f2tf32(v.y);
            u.z = f2tf32(v.z); u.w = f2tf32(v.w);
            *(uint4*)&sB[bk2][bn2 + i * 4] = u;
        }
        __syncthreads();

        #pragma unroll
        for (int ks = 0; ks < 4; ks++) {
            const int kk = ks * 8;
            uint32_t af[2][4];
            #pragma unroll
            for (int mt = 0; mt < 2; mt++) {
                int mb = wm * 32 + mt * 16 + g;
                af[mt][0] = sA[kk + t4    ][mb];
                af[mt][1] = sA[kk + t4    ][mb + 8];
                af[mt][2] = sA[kk + t4 + 4][mb];
                af[mt][3] = sA[kk + t4 + 4][mb + 8];
            }
            uint32_t bf[4][2];
            #pragma unroll
            for (int nt = 0; nt < 4; nt++) {
                int nb = wn * 32 + nt * 8 + g;
                bf[nt][0] = sB[kk + t4    ][nb];
                bf[nt][1] = sB[kk + t4 + 4][nb];
            }
            #pragma unroll
            for (int mt = 0; mt < 2; mt++)
                #pragma unroll
                for (int nt = 0; nt < 4; nt++) {
                    asm("mma.sync.aligned.m16n8k8.row.col.f32.tf32.tf32.f32 "
                        "{%0,%1,%2,%3}, {%4,%5,%6,%7}, {%8,%9}, {%0,%1,%2,%3};"
                        : "+f"(acc[mt][nt][0]), "+f"(acc[mt][nt][1]),
                          "+f"(acc[mt][nt][2]), "+f"(acc[mt][nt][3])
                        : "r"(af[mt][0]), "r"(af[mt][1]),
                          "r"(af[mt][2]), "r"(af[mt][3]),
                          "r"(bf[nt][0]), "r"(bf[nt][1]));
                }
        }
        __syncthreads();
    }

    // epilogue: C[row][col] = (acc + bias) * scale
    #pragma unroll
    for (int nt = 0; nt < 4; nt++) {
        int col = n0 + wn * 32 + nt * 8 + 2 * t4;
        float b0v = bias[col], b1v = bias[col + 1];
        #pragma unroll
        for (int mt = 0; mt < 2; mt++) {
            int row = m0 + wm * 32 + mt * 16 + g;
            float2 o;
            o.x = (acc[mt][nt][0] + b0v) * scale;
            o.y = (acc[mt][nt][1] + b1v) * scale;
            *(float2*)&C[(size_t)row * E + col] = o;
            o.x = (acc[mt][nt][2] + b0v) * scale;
            o.y = (acc[mt][nt][3] + b1v) * scale;
            *(float2*)&C[(size_t)(row + 8) * E + col] = o;
        }
    }
}

// ---------------- lam ----------------
__global__ __launch_bounds__(256) void lam_kernel(
    const float* __restrict__ Wlqc, const float* __restrict__ blqc,
    const float* __restrict__ Wlqq, const float* __restrict__ blqq,
    const float* __restrict__ Wlkc, const float* __restrict__ blkc,
    const float* __restrict__ Wlkk, const float* __restrict__ blkk)
{
    int gw   = (blockIdx.x * blockDim.x + threadIdx.x) >> 5;
    int lane = threadIdx.x & 31;
    if (gw >= S * Hh) return;
    int s = gw / Hh, h = gw % Hh;
    size_t base = (size_t)s * E + h * D;

    float a = g_cq[base + lane] * Wlqc[lane] + g_cq[base + lane + 32] * Wlqc[lane + 32]
            + g_q [base + lane] * Wlqq[lane] + g_q [base + lane + 32] * Wlqq[lane + 32];
    float b = g_ck[base + lane] * Wlkc[lane] + g_ck[base + lane + 32] * Wlkc[lane + 32]
            + g_k [base + lane] * Wlkk[lane] + g_k [base + lane + 32] * Wlkk[lane + 32];
    #pragma unroll
    for (int o = 16; o; o >>= 1) {
        a += __shfl_xor_sync(0xffffffffu, a, o);
        b += __shfl_xor_sync(0xffffffffu, b, o);
    }
    if (lane == 0) {
        float lq = 1.f / (1.f + __expf(-(a + blqc[0] + blqq[0])));
        float lk = 1.f / (1.f + __expf(-(b + blkc[0] + blkk[0])));
        g_lam[gw] = 1.f - lq - lk;
    }
}

// ---------------- quasi kernel: npout[t] = lam * sigmoid(cq.cq + mask)  (stream-through) ----------------
#define KSTR 64

__global__ __launch_bounds__(256) void quasi_kernel(
    const int* __restrict__ amask, float* __restrict__ npout)
{
    __shared__ float sCQT[64 * TQ];    // cq^T for query rows
    __shared__ float sCKT[64 * KSTR];  // cq key-block^T
    __shared__ float sFm[64];

    const int h   = blockIdx.y;
    const int q0  = blockIdx.x * TQ;
    const int tid = threadIdx.x;
    const int rg  = tid >> 4;          // 0..15
    const int cg  = tid & 15;
    const int r0  = rg << 1;           // rows r0, r0+1
    const int c0  = cg << 2;           // cols c0..c0+3

    {
        int lr = tid >> 3;             // 0..31
        int d0 = (tid & 7) << 3;       // 8 floats each
        const float4* cqp = (const float4*)(g_cq + (size_t)(q0 + lr) * E + h * D + d0);
        float4 c1 = cqp[0], c2 = cqp[1];
        sCQT[(d0+0)*TQ + lr] = c1.x; sCQT[(d0+1)*TQ + lr] = c1.y;
        sCQT[(d0+2)*TQ + lr] = c1.z; sCQT[(d0+3)*TQ + lr] = c1.w;
        sCQT[(d0+4)*TQ + lr] = c2.x; sCQT[(d0+5)*TQ + lr] = c2.y;
        sCQT[(d0+6)*TQ + lr] = c2.z; sCQT[(d0+7)*TQ + lr] = c2.w;
    }

    const float lam0 = g_lam[(q0 + r0 + 0) * Hh + h];
    const float lam1 = g_lam[(q0 + r0 + 1) * Hh + h];
    float* nprow0 = npout + ((size_t)(q0 + r0 + 0) * Hh + h) * TT;
    float* nprow1 = npout + ((size_t)(q0 + r0 + 1) * Hh + h) * TT;

    const int lc  = tid >> 2;          // 0..63
    const int ld0 = (tid & 3) << 4;    // 0,16,32,48

    for (int b = 0; b < NKB; b++) {
        const int kb0 = q0 - Wb + b * 64;
        __syncthreads();
        {
            int j = kb0 + lc;
            bool ok = (j >= 0) && (j < S);
            const float4* cp = (const float4*)(g_cq + (size_t)(ok ? j : 0) * E + h * D + ld0);
            #pragma unroll
            for (int u4 = 0; u4 < 4; u4++) {
                float4 cv = ok ? cp[u4] : make_float4(0.f,0.f,0.f,0.f);
                int dd = ld0 + u4 * 4;
                sCKT[(dd+0)*KSTR + lc] = cv.x; sCKT[(dd+1)*KSTR + lc] = cv.y;
                sCKT[(dd+2)*KSTR + lc] = cv.z; sCKT[(dd+3)*KSTR + lc] = cv.w;
            }
            if (tid < 64) {
                int jj = kb0 + tid;
                sFm[tid] = (jj >= 0 && jj < S && amask[jj] != 0) ? -10000.f : 0.f;
            }
        }
        __syncthreads();

        float acq[2][4] = {{0.f,0.f,0.f,0.f},{0.f,0.f,0.f,0.f}};
        #pragma unroll 8
        for (int kk = 0; kk < 64; kk++) {
            float2 cqv = *(const float2*)&sCQT[kk*TQ  + r0];
            float4 ckv = *(const float4*)&sCKT[kk*KSTR + c0];
            acq[0][0] += cqv.x*ckv.x; acq[0][1] += cqv.x*ckv.y;
            acq[0][2] += cqv.x*ckv.z; acq[0][3] += cqv.x*ckv.w;
            acq[1][0] += cqv.y*ckv.x; acq[1][1] += cqv.y*ckv.y;
            acq[1][2] += cqv.y*ckv.z; acq[1][3] += cqv.y*ckv.w;
        }

        #pragma unroll
        for (int jx = 0; jx < 4; jx++) {
            int c = c0 + jx;
            int j = kb0 + c;
            bool okj = (j >= 0) && (j < S);
            float fm = sFm[c];
            {
                int t = b * 64 + c - (r0 + 0);
                if (t >= 0 && t <= 512) {
                    float v = okj ? lam0 / (1.f + __expf(-(acq[0][jx] + fm))) : 0.f;
                    nprow0[t] = v;
                }
            }
            {
                int t = b * 64 + c - (r0 + 1);
                if (t >= 0 && t <= 512) {
                    float v = okj ? lam1 / (1.f + __expf(-(acq[1][jx] + fm))) : 0.f;
                    nprow1[t] = v;
                }
            }
        }
    }
}

// ---------------- attn kernel: softmax band + combine with staged quasi ----------------
__global__ __launch_bounds__(256, 2) void attn_kernel(
    const int* __restrict__ amask, float* __restrict__ npout)
{
    __shared__ float sQT[64 * TQ];     // q^T (pre-scaled)
    __shared__ float sKT[64 * KSTR];   // k^T
    __shared__ float sFm[64];

    const int h   = blockIdx.y;
    const int q0  = blockIdx.x * TQ;
    const int tid = threadIdx.x;
    const int rg  = tid >> 4;
    const int cg  = tid & 15;
    const int r0  = rg << 1;
    const int c0  = cg << 2;

    {
        int lr = tid >> 3;
        int d0 = (tid & 7) << 3;
        const float4* qp = (const float4*)(g_q + (size_t)(q0 + lr) * E + h * D + d0);
        float4 q1 = qp[0], q2 = qp[1];
        sQT[(d0+0)*TQ + lr] = q1.x * SCALE; sQT[(d0+1)*TQ + lr] = q1.y * SCALE;
        sQT[(d0+2)*TQ + lr] = q1.z * SCALE; sQT[(d0+3)*TQ + lr] = q1.w * SCALE;
        sQT[(d0+4)*TQ + lr] = q2.x * SCALE; sQT[(d0+5)*TQ + lr] = q2.y * SCALE;
        sQT[(d0+6)*TQ + lr] = q2.z * SCALE; sQT[(d0+7)*TQ + lr] = q2.w * SCALE;
    }

    float aA[2][NKB*4];   // attn band (scores, then exp)

    const int lc  = tid >> 2;
    const int ld0 = (tid & 3) << 4;

    #pragma unroll
    for (int b = 0; b < NKB; b++) {
        const int kb0 = q0 - Wb + b * 64;
        __syncthreads();
        {
            int j = kb0 + lc;
            bool ok = (j >= 0) && (j < S);
            const float4* kp = (const float4*)(g_k + (size_t)(ok ? j : 0) * E + h * D + ld0);
            #pragma unroll
            for (int u4 = 0; u4 < 4; u4++) {
                float4 kv = ok ? kp[u4] : make_float4(0.f,0.f,0.f,0.f);
                int dd = ld0 + u4 * 4;
                sKT[(dd+0)*KSTR + lc] = kv.x; sKT[(dd+1)*KSTR + lc] = kv.y;
                sKT[(dd+2)*KSTR + lc] = kv.z; sKT[(dd+3)*KSTR + lc] = kv.w;
            }
            if (tid < 64) {
                int jj = kb0 + tid;
                sFm[tid] = (jj >= 0 && jj < S && amask[jj] != 0) ? -10000.f : 0.f;
            }
        }
        __syncthreads();

        float acc[2][4] = {{0.f,0.f,0.f,0.f},{0.f,0.f,0.f,0.f}};
        #pragma unroll 8
        for (int kk = 0; kk < 64; kk++) {
            float2 qv = *(const float2*)&sQT[kk*TQ  + r0];
            float4 kv = *(const float4*)&sKT[kk*KSTR + c0];
            acc[0][0] += qv.x*kv.x; acc[0][1] += qv.x*kv.y;
            acc[0][2] += qv.x*kv.z; acc[0][3] += qv.x*kv.w;
            acc[1][0] += qv.y*kv.x; acc[1][1] += qv.y*kv.y;
            acc[1][2] += qv.y*kv.z; acc[1][3] += qv.y*kv.w;
        }

        #pragma unroll
        for (int i = 0; i < 2; i++) {
            int r = r0 + i;
            #pragma unroll
            for (int jx = 0; jx < 4; jx++) {
                int c = c0 + jx;
                int t = b * 64 + c - r;
                int j = kb0 + c;
                bool valid = (t >= 0) && (t <= 512) && (j >= 0) && (j < S);
                aA[i][b*4+jx] = valid ? (acc[i][jx] + sFm[c]) : NEGV;
            }
        }
    }

    #pragma unroll
    for (int i = 0; i < 2; i++) {
        int r  = r0 + i;
        int ig = q0 + r;
        float m = NEGV;
        #pragma unroll
        for (int x = 0; x < NKB*4; x++) m = fmaxf(m, aA[i][x]);
        #pragma unroll
        for (int o = 8; o; o >>= 1) m = fmaxf(m, __shfl_xor_sync(0xffffffffu, m, o));
        float ssum = 0.f;
        #pragma unroll
        for (int x = 0; x < NKB*4; x++) {
            float e = __expf(aA[i][x] - m);
            aA[i][x] = e;
            ssum += e;
        }
        #pragma unroll
        for (int o = 8; o; o >>= 1) ssum += __shfl_xor_sync(0xffffffffu, ssum, o);
        float inv = 1.f / ssum;
        bool  qm  = (amask[ig] != 0);
        float* nprow = npout + ((size_t)ig * Hh + h) * TT;
        #pragma unroll
        for (int b = 0; b < NKB; b++) {
            #pragma unroll
            for (int jx = 0; jx < 4; jx++) {
                int t = b * 64 + c0 + jx - r;
                if (t >= 0 && t <= 512) {
                    float np = aA[i][b*4+jx] * inv + nprow[t];
                    nprow[t] = qm ? 0.f : np;
                }
            }
        }
    }
}

// ---------------- PV: out = band_pv(new_probs, v) ----------------
#define PSTR 68
#define VSTR 68

__global__ __launch_bounds__(256) void pv_kernel(
    float* __restrict__ outp, const float* __restrict__ npout)
{
    __shared__ float sP[TQP * PSTR];   // [64][68]
    __shared__ float sV[64 * VSTR];    // [64][68]

    const int h   = blockIdx.y;
    const int q0  = blockIdx.x * TQP;
    const int tid = threadIdx.x;
    const int rg  = tid >> 4;          // rows 4rg..4rg+3
    const int dg  = tid & 15;          // d = 4dg..4dg+3

    float acc[4][4];
    #pragma unroll
    for (int i = 0; i < 4; i++)
        #pragma unroll
        for (int j = 0; j < 4; j++) acc[i][j] = 0.f;

    for (int b = 0; b < NKB; b++) {
        int kb0 = q0 - Wb + b * 64;
        __syncthreads();
        {
            int lr  = tid >> 2;
            int c0l = (tid & 3) << 4;
            const float* nprow = npout + ((size_t)(q0 + lr) * Hh + h) * TT;
            #pragma unroll
            for (int x4 = 0; x4 < 4; x4++) {
                int t0 = b * 64 + c0l + x4 * 4 - lr;
                float4 pv4;
                pv4.x = (t0+0 >= 0 && t0+0 <= 512) ? nprow[t0+0] : 0.f;
                pv4.y = (t0+1 >= 0 && t0+1 <= 512) ? nprow[t0+1] : 0.f;
                pv4.z = (t0+2 >= 0 && t0+2 <= 512) ? nprow[t0+2] : 0.f;
                pv4.w = (t0+3 >= 0 && t0+3 <= 512) ? nprow[t0+3] : 0.f;
                *(float4*)&sP[lr * PSTR + c0l + x4 * 4] = pv4;
            }
        }
        {
            int c   = tid >> 2;
            int d0l = (tid & 3) << 4;
            int j = kb0 + c;
            bool ok = (j >= 0) && (j < S);
            const float4* vp = (const float4*)(g_v + (size_t)(ok ? j : 0) * E + h * D + d0l);
            #pragma unroll
            for (int u4 = 0; u4 < 4; u4++) {
                float4 x = ok ? vp[u4] : make_float4(0.f,0.f,0.f,0.f);
                *(float4*)&sV[c * VSTR + d0l + u4 * 4] = x;
            }
        }
        __syncthreads();

        #pragma unroll 4
        for (int c = 0; c < 64; c++) {
            float4 vv = *(const float4*)&sV[c * VSTR + 4 * dg];
            float p0 = sP[(4*rg+0) * PSTR + c];
            float p1 = sP[(4*rg+1) * PSTR + c];
            float p2 = sP[(4*rg+2) * PSTR + c];
            float p3 = sP[(4*rg+3) * PSTR + c];
            acc[0][0] += p0*vv.x; acc[0][1] += p0*vv.y; acc[0][2] += p0*vv.z; acc[0][3] += p0*vv.w;
            acc[1][0] += p1*vv.x; acc[1][1] += p1*vv.y; acc[1][2] += p1*vv.z; acc[1][3] += p1*vv.w;
            acc[2][0] += p2*vv.x; acc[2][1] += p2*vv.y; acc[2][2] += p2*vv.z; acc[2][3] += p2*vv.w;
            acc[3][0] += p3*vv.x; acc[3][1] += p3*vv.y; acc[3][2] += p3*vv.z; acc[3][3] += p3*vv.w;
        }
    }

    #pragma unroll
    for (int i = 0; i < 4; i++) {
        float4 o;
        o.x = acc[i][0]; o.y = acc[i][1]; o.z = acc[i][2]; o.w = acc[i][3];
        *(float4*)(outp + (size_t)(q0 + 4*rg + i) * E + h * D + 4 * dg) = o;
    }
}

// ---------------- launch ----------------
extern "C" void kernel_launch(void* const* d_in, const int* in_sizes, int n_in,
                              void* d_out, int out_size)
{
    (void)in_sizes; (void)n_in; (void)out_size;

    const float* hs    = (const float*)d_in[0];
    const float* ce    = (const float*)d_in[1];
    const int*   amask = (const int*)  d_in[2];
    // d_in[3] is is_index_masked == (attention_mask != 0); derived from amask.
    const float* Wq   = (const float*)d_in[4];
    const float* bq   = (const float*)d_in[5];
    const float* Wk   = (const float*)d_in[6];
    const float* bk   = (const float*)d_in[7];
    const float* Wv   = (const float*)d_in[8];
    const float* bv   = (const float*)d_in[9];
    const float* Wcq  = (const float*)d_in[10];
    const float* bcq  = (const float*)d_in[11];
    const float* Wck  = (const float*)d_in[12];
    const float* bck  = (const float*)d_in[13];
    const float* Wlqc = (const float*)d_in[14];
    const float* blqc = (const float*)d_in[15];
    const float* Wlqq = (const float*)d_in[16];
    const float* blqq = (const float*)d_in[17];
    const float* Wlkc = (const float*)d_in[18];
    const float* blkc = (const float*)d_in[19];
    const float* Wlkk = (const float*)d_in[20];
    const float* blkk = (const float*)d_in[21];

    float* outp  = (float*)d_out;
    float* npout = outp + (size_t)S * E;   // tuple output: [out | new_probs]

    dim3 gg(E / GBN, S / GBM, 5);
    gemm5_tc<<<gg, 256>>>(hs, ce, Wq, bq, Wk, bk, Wv, bv, Wcq, bcq, Wck, bck);

    lam_kernel<<<(S * Hh) / 8, 256>>>(Wlqc, blqc, Wlqq, blqq, Wlkc, blkc, Wlkk, blkk);

    quasi_kernel<<<dim3(S / TQ, Hh), 256>>>(amask, npout);

    attn_kernel<<<dim3(S / TQ, Hh), 256>>>(amask, npout);

    pv_kernel<<<dim3(S / TQP, Hh), 256>>>(outp, npout);
}